// round 3
// baseline (speedup 1.0000x reference)
#include <cuda_runtime.h>
#include <cuda_bf16.h>

// Global scratch (zero-initialized at module load; reset by the last block
// every launch so each graph replay starts clean).
__device__ double        g_acc;
__device__ unsigned int  g_count;

// Each warp handles 128 rows (96 float4 per array), loaded coalesced and
// re-aligned to rows via a warp-local shared-memory tile.
// Block = 256 threads = 8 warps = 1024 rows per block.
__global__ void __launch_bounds__(256) range_loss_kernel(
    const float4* __restrict__ preds4,
    const float4* __restrict__ target4,
    float* __restrict__ out,
    double inv_count,
    unsigned int nblocks)
{
    __shared__ float4 s_p[8 * 96];   // 12 KB
    __shared__ float4 s_t[8 * 96];   // 12 KB

    const int lane = threadIdx.x & 31;
    const int wid  = threadIdx.x >> 5;

    // Warp's base in float4 units (96 float4 per warp per array).
    const unsigned warp_f4 = (blockIdx.x * 8u + (unsigned)wid) * 96u;

    float4* sp = s_p + wid * 96;
    float4* st = s_t + wid * 96;

    // Fully coalesced global loads: each LDG.128 covers 512 contiguous bytes.
    #pragma unroll
    for (int k = 0; k < 3; k++)
        sp[lane + 32 * k] = preds4[warp_f4 + lane + 32 * k];
    #pragma unroll
    for (int k = 0; k < 3; k++)
        st[lane + 32 * k] = target4[warp_f4 + lane + 32 * k];

    __syncwarp();

    // Row-aligned reads: float4 at smem index lane*3+k (conflict-free:
    // byte addr lane*48 -> banks 12*lane mod 32 + 4 consecutive, full cover).
    float4 p4a = sp[lane * 3 + 0];
    float4 p4b = sp[lane * 3 + 1];
    float4 p4c = sp[lane * 3 + 2];
    float4 t4a = st[lane * 3 + 0];
    float4 t4b = st[lane * 3 + 1];
    float4 t4c = st[lane * 3 + 2];

    float p[12], t[12];
    p[0]=p4a.x; p[1]=p4a.y; p[2]=p4a.z; p[3]=p4a.w;
    p[4]=p4b.x; p[5]=p4b.y; p[6]=p4b.z; p[7]=p4b.w;
    p[8]=p4c.x; p[9]=p4c.y; p[10]=p4c.z; p[11]=p4c.w;
    t[0]=t4a.x; t[1]=t4a.y; t[2]=t4a.z; t[3]=t4a.w;
    t[4]=t4b.x; t[5]=t4b.y; t[6]=t4b.z; t[7]=t4b.w;
    t[8]=t4c.x; t[9]=t4c.y; t[10]=t4c.z; t[11]=t4c.w;

    float acc = 0.0f;
    #pragma unroll
    for (int r = 0; r < 4; r++) {
        float p0 = p[3*r + 0], p1 = p[3*r + 1], p2 = p[3*r + 2];
        float t0 = t[3*r + 0], t1 = t[3*r + 1], t2 = t[3*r + 2];

        // t0 rewrite (conditions mutually exclusive)
        if ((p0 < 0.1f && t0 == 0.0f) || (p0 > 0.9f && t0 == 1.0f)) t0 = p0;
        // t2 rewrite
        if ((p2 < 0.1f && t2 == 0.0f) || (p2 > 0.9f && t2 == 1.0f)) t2 = p2;
        // t1 rewrite: depends on p2 of the SAME row and the ORIGINAL t1.
        // 1.0+RANGE / 1.0-RANGE round to exactly 1.02f / 0.98f in fp32.
        bool in_range = (p1 * 1.02f > t1) && (p1 * 0.98f < t1);
        if ((p2 > 0.9f) || in_range) t1 = p1;

        float d0 = p0 - t0;
        float d1 = p1 - t1;
        float d2 = p2 - t2;
        acc += d0 * d0 + d1 * d1 + d2 * d2;
    }

    // Warp reduction
    #pragma unroll
    for (int o = 16; o > 0; o >>= 1)
        acc += __shfl_xor_sync(0xffffffffu, acc, o);

    // Cross-warp reduction in shared memory
    __shared__ float warp_sums[8];
    if (lane == 0) warp_sums[wid] = acc;
    __syncthreads();

    if (wid == 0) {
        float v = (lane < 8) ? warp_sums[lane] : 0.0f;
        #pragma unroll
        for (int o = 4; o > 0; o >>= 1)
            v += __shfl_xor_sync(0xffffffffu, v, o);

        if (lane == 0) {
            atomicAdd(&g_acc, (double)v);
            __threadfence();
            unsigned int done = atomicAdd(&g_count, 1u);
            if (done == nblocks - 1u) {
                // Last block: read+reset accumulator atomically, write result,
                // reset counter for the next replay.
                unsigned long long raw =
                    atomicExch((unsigned long long*)&g_acc, 0ull);
                double total = __longlong_as_double(raw);
                out[0] = (float)(total * inv_count);
                atomicExch(&g_count, 0u);
            }
        }
    }
}

extern "C" void kernel_launch(void* const* d_in, const int* in_sizes, int n_in,
                              void* d_out, int out_size)
{
    const float4* preds4  = (const float4*)d_in[0];
    const float4* target4 = (const float4*)d_in[1];
    float* out = (float*)d_out;

    const long long nelem = (long long)in_sizes[0];  // N * 3 = 25165824
    const long long nrows = nelem / 3;               // 8388608
    const int block = 256;
    // 1024 rows per block
    const unsigned int grid = (unsigned int)((nrows + 1023) / 1024);

    range_loss_kernel<<<grid, block>>>(preds4, target4, out,
                                       1.0 / (double)nelem, grid);
}

// round 4
// speedup vs baseline: 1.0539x; 1.0539x over previous
#include <cuda_runtime.h>
#include <cuda_bf16.h>

// Global scratch (zero-initialized at module load; reset by the last block
// every launch so each graph replay starts clean).
__device__ double        g_acc;
__device__ unsigned int  g_count;

// Each thread handles 8 rows = 24 floats = 6 float4 loads per input array,
// all issued up front (12 outstanding LDG.128 per thread) to maximize MLP.
__global__ void __launch_bounds__(256, 4) range_loss_kernel(
    const float4* __restrict__ preds4,
    const float4* __restrict__ target4,
    float* __restrict__ out,
    double inv_count,
    unsigned int nblocks)
{
    const unsigned tid  = blockIdx.x * blockDim.x + threadIdx.x;
    const unsigned base = tid * 6u;   // float4 index; 6 float4 = 8 rows

    // Streaming loads (single-touch data: evict-first in L2).
    float4 pv[6], tv[6];
    #pragma unroll
    for (int k = 0; k < 6; k++) pv[k] = __ldcs(&preds4[base + k]);
    #pragma unroll
    for (int k = 0; k < 6; k++) tv[k] = __ldcs(&target4[base + k]);

    const float* p = (const float*)pv;   // 24 floats = 8 rows
    const float* t = (const float*)tv;

    float acc = 0.0f;
    #pragma unroll
    for (int r = 0; r < 8; r++) {
        float p0 = p[3*r + 0], p1 = p[3*r + 1], p2 = p[3*r + 2];
        float t0 = t[3*r + 0], t1 = t[3*r + 1], t2 = t[3*r + 2];

        // t0 rewrite (conditions mutually exclusive)
        if ((p0 < 0.1f && t0 == 0.0f) || (p0 > 0.9f && t0 == 1.0f)) t0 = p0;
        // t2 rewrite
        if ((p2 < 0.1f && t2 == 0.0f) || (p2 > 0.9f && t2 == 1.0f)) t2 = p2;
        // t1 rewrite: depends on p2 of the SAME row and the ORIGINAL t1.
        // 1.0+RANGE / 1.0-RANGE round to exactly 1.02f / 0.98f in fp32.
        bool in_range = (p1 * 1.02f > t1) && (p1 * 0.98f < t1);
        if ((p2 > 0.9f) || in_range) t1 = p1;

        float d0 = p0 - t0;
        float d1 = p1 - t1;
        float d2 = p2 - t2;
        acc += d0 * d0 + d1 * d1 + d2 * d2;
    }

    // Warp reduction
    #pragma unroll
    for (int o = 16; o > 0; o >>= 1)
        acc += __shfl_xor_sync(0xffffffffu, acc, o);

    // Cross-warp reduction in shared memory
    __shared__ float warp_sums[8];
    const int lane = threadIdx.x & 31;
    const int wid  = threadIdx.x >> 5;
    if (lane == 0) warp_sums[wid] = acc;
    __syncthreads();

    if (wid == 0) {
        float v = (lane < 8) ? warp_sums[lane] : 0.0f;
        #pragma unroll
        for (int o = 4; o > 0; o >>= 1)
            v += __shfl_xor_sync(0xffffffffu, v, o);

        if (lane == 0) {
            atomicAdd(&g_acc, (double)v);
            __threadfence();
            unsigned int done = atomicAdd(&g_count, 1u);
            if (done == nblocks - 1u) {
                // Last block: read+reset accumulator atomically, write result,
                // reset counter for the next replay.
                unsigned long long raw =
                    atomicExch((unsigned long long*)&g_acc, 0ull);
                double total = __longlong_as_double(raw);
                out[0] = (float)(total * inv_count);
                atomicExch(&g_count, 0u);
            }
        }
    }
}

extern "C" void kernel_launch(void* const* d_in, const int* in_sizes, int n_in,
                              void* d_out, int out_size)
{
    const float4* preds4  = (const float4*)d_in[0];
    const float4* target4 = (const float4*)d_in[1];
    float* out = (float*)d_out;

    const long long nelem    = (long long)in_sizes[0];  // N * 3 = 25165824
    const long long nrows    = nelem / 3;               // 8388608
    const long long nthreads = nrows / 8;               // 8 rows / thread
    const int block = 256;
    const unsigned int grid = (unsigned int)((nthreads + block - 1) / block);

    range_loss_kernel<<<grid, block>>>(preds4, target4, out,
                                       1.0 / (double)nelem, grid);
}

// round 5
// speedup vs baseline: 1.0952x; 1.0391x over previous
#include <cuda_runtime.h>
#include <cuda_bf16.h>

// Global scratch (zero-initialized at module load; reset by the last block
// every launch so each graph replay starts clean).
__device__ double        g_acc;
__device__ unsigned int  g_count;

// Perfectly-coalesced element-parallel formulation.
// Key identity: every rewrite sets t <- p, so the per-element diff is
//   col 0/2: z = (p<0.1 && t==0) || (p>0.9 && t==1)      -> d = z ? 0 : p-t
//   col 1  : z = (p_next>0.9) || (1.02p > t && 0.98p < t) -> d = z ? 0 : p-t
// The only cross-element need is p[e+1] for col-1 elements, obtained via
// __shfl_down (lane 31 patches the boundary with one predicated scalar load).
__global__ void __launch_bounds__(256) range_loss_kernel(
    const float4* __restrict__ preds4,
    const float4* __restrict__ target4,
    const float*  __restrict__ preds_flat,
    float* __restrict__ out,
    double inv_count,
    unsigned int nblocks,
    unsigned int last_elem)   // nelem - 1
{
    const int lane = threadIdx.x & 31;
    const int wid  = threadIdx.x >> 5;
    const unsigned base = blockIdx.x * 1024u + threadIdx.x; // float4 index

    // 8 front-batched, fully coalesced LDG.128 (nL = 4 lines each).
    float4 pv[4], tv[4];
    #pragma unroll
    for (int k = 0; k < 4; k++) pv[k] = __ldcs(&preds4[base + 256u * k]);
    #pragma unroll
    for (int k = 0; k < 4; k++) tv[k] = __ldcs(&target4[base + 256u * k]);

    // Neighbor value p[4g+4] per chunk (needed when element j=3 is col-1).
    float nx[4];
    #pragma unroll
    for (int k = 0; k < 4; k++) {
        float v = __shfl_down_sync(0xffffffffu, pv[k].x, 1);
        if (lane == 31) {
            unsigned g   = base + 256u * k;
            unsigned idx = 4u * (g + 1u);
            if (idx > last_elem) idx = last_elem;  // clamp; value unused there
            v = preds_flat[idx];
        }
        nx[k] = v;
    }

    float acc = 0.0f;
    #pragma unroll
    for (int k = 0; k < 4; k++) {
        const unsigned g = base + 256u * k;
        const unsigned r = g % 3u;   // col of element 4g is (4g)%3 = g%3

        float pe[4] = { pv[k].x, pv[k].y, pv[k].z, pv[k].w };
        float te[4] = { tv[k].x, tv[k].y, tv[k].z, tv[k].w };
        float pn[4] = { pv[k].y, pv[k].z, pv[k].w, nx[k] };

        #pragma unroll
        for (int j = 0; j < 4; j++) {
            // col of element = (r + j) % 3; per unrolled j this is one compare.
            bool is1;
            if      (j == 0) is1 = (r == 1u);
            else if (j == 1) is1 = (r == 0u);
            else if (j == 2) is1 = (r == 2u);
            else             is1 = (r == 1u);

            float p = pe[j], t = te[j];
            bool z02 = (p < 0.1f && t == 0.0f) || (p > 0.9f && t == 1.0f);
            // 1.0+RANGE / 1.0-RANGE round to exactly 1.02f / 0.98f in fp32.
            bool zin = (p * 1.02f > t) && (p * 0.98f < t);
            bool z1  = (pn[j] > 0.9f) || zin;
            bool z   = is1 ? z1 : z02;
            float d  = z ? 0.0f : (p - t);
            acc += d * d;
        }
    }

    // Warp reduction
    #pragma unroll
    for (int o = 16; o > 0; o >>= 1)
        acc += __shfl_xor_sync(0xffffffffu, acc, o);

    // Cross-warp reduction in shared memory
    __shared__ float warp_sums[8];
    if (lane == 0) warp_sums[wid] = acc;
    __syncthreads();

    if (wid == 0) {
        float v = (lane < 8) ? warp_sums[lane] : 0.0f;
        #pragma unroll
        for (int o = 4; o > 0; o >>= 1)
            v += __shfl_xor_sync(0xffffffffu, v, o);

        if (lane == 0) {
            atomicAdd(&g_acc, (double)v);
            __threadfence();
            unsigned int done = atomicAdd(&g_count, 1u);
            if (done == nblocks - 1u) {
                unsigned long long raw =
                    atomicExch((unsigned long long*)&g_acc, 0ull);
                double total = __longlong_as_double(raw);
                out[0] = (float)(total * inv_count);
                atomicExch(&g_count, 0u);
            }
        }
    }
}

extern "C" void kernel_launch(void* const* d_in, const int* in_sizes, int n_in,
                              void* d_out, int out_size)
{
    const float4* preds4     = (const float4*)d_in[0];
    const float4* target4    = (const float4*)d_in[1];
    const float*  preds_flat = (const float*)d_in[0];
    float* out = (float*)d_out;

    const long long nelem = (long long)in_sizes[0];   // N*3 = 25165824
    const long long nf4   = nelem / 4;                // 6291456 float4
    // 1024 float4 per block (4 chunks x 256 threads)
    const unsigned int grid = (unsigned int)((nf4 + 1023) / 1024);

    range_loss_kernel<<<grid, 256>>>(preds4, target4, preds_flat, out,
                                     1.0 / (double)nelem, grid,
                                     (unsigned int)(nelem - 1));
}